// round 1
// baseline (speedup 1.0000x reference)
#include <cuda_runtime.h>

// MHA forward, B=4 H=16 S=2048 Dk=4, outputs BOTH out [B,H,S,4] and attn [B,H,S,S].
// d_out layout assumed: out (524288 f32) followed by attn (268435456 f32).
//
// Strategy: HBM-write-bound on attn (1.07 GB). Block = (b, tile of 16 queries),
// warp = one query row, loop over 16 heads with K/V staged in 64KB dynamic smem.
// Mask row packed into 2 register bitmasks per lane, reused across all heads.
// Each lane owns 4 consecutive k's -> float4 (STG.128) attn writes; smem holds
// K/V in a component-swizzled layout so those accesses are conflict-free LDS.128.

#define SQ      2048
#define QT      16
#define NH      16
#define NB      4
#define THREADS 512
#define SQ4     (SQ / 4)

__global__ __launch_bounds__(THREADS, 1)
void mha_kernel(const float4* __restrict__ Q, const float4* __restrict__ K,
                const float4* __restrict__ V, const int*    __restrict__ mask,
                float4* __restrict__ out, float4* __restrict__ attn)
{
    extern __shared__ float4 sm[];
    float4* Ks = sm;        // swizzled: logical k stored at (k&3)*SQ4 + (k>>2)
    float4* Vs = sm + SQ;

    const int qt   = blockIdx.x;
    const int b    = blockIdx.y;
    const int tid  = threadIdx.x;
    const int w    = tid >> 5;
    const int lane = tid & 31;
    const int q    = qt * QT + w;

    // ---- pack mask row into 64 bits per lane (bit i*4+j = mask for k=(i*32+lane)*4+j)
    const int4* mrow = (const int4*)mask + ((size_t)b * SQ + q) * (size_t)SQ4;
    unsigned mb0 = 0u, mb1 = 0u;
#pragma unroll
    for (int i = 0; i < 16; ++i) {
        int4 mv = mrow[i * 32 + lane];
        unsigned bits = (mv.x != 0 ? 1u : 0u) | (mv.y != 0 ? 2u : 0u)
                      | (mv.z != 0 ? 4u : 0u) | (mv.w != 0 ? 8u : 0u);
        if (i < 8) mb0 |= bits << (i * 4);
        else       mb1 |= bits << ((i - 8) * 4);
    }

    float sc[16][4];

    for (int h = 0; h < NH; ++h) {
        const int bh = b * NH + h;

        __syncthreads();  // previous head's smem reads done
        {
            const float4* Kb = K + (size_t)bh * SQ;
            const float4* Vb = V + (size_t)bh * SQ;
            for (int t = tid; t < SQ; t += THREADS) {
                int si = (t & 3) * SQ4 + (t >> 2);
                Ks[si] = Kb[t];
                Vs[si] = Vb[t];
            }
        }
        __syncthreads();

        const float4 qv = Q[(size_t)bh * SQ + q];

        // ---- pass 1: scores + row max
        float m = -1e30f;
#pragma unroll
        for (int i = 0; i < 16; ++i) {
            const unsigned mb = (i < 8) ? mb0 : mb1;
            const int sh = (i & 7) * 4;
#pragma unroll
            for (int j = 0; j < 4; ++j) {
                float4 kv = Ks[j * SQ4 + i * 32 + lane];
                float s = 0.5f * (qv.x * kv.x + qv.y * kv.y + qv.z * kv.z + qv.w * kv.w);
                s = ((mb >> (sh + j)) & 1u) ? s : -1e9f;
                sc[i][j] = s;
                m = fmaxf(m, s);
            }
        }
#pragma unroll
        for (int o = 16; o; o >>= 1) m = fmaxf(m, __shfl_xor_sync(0xffffffffu, m, o));

        // ---- pass 2: exp + row sum
        float sum = 0.f;
#pragma unroll
        for (int i = 0; i < 16; ++i) {
#pragma unroll
            for (int j = 0; j < 4; ++j) {
                float e = __expf(sc[i][j] - m);
                sc[i][j] = e;
                sum += e;
            }
        }
#pragma unroll
        for (int o = 16; o; o >>= 1) sum += __shfl_xor_sync(0xffffffffu, sum, o);
        const float inv = 1.0f / sum;

        // ---- pass 3: write attn (STG.128) + accumulate out = attn @ V
        float4* arow = attn + ((size_t)bh * SQ + q) * (size_t)SQ4;
        float ax = 0.f, ay = 0.f, az = 0.f, aw = 0.f;
#pragma unroll
        for (int i = 0; i < 16; ++i) {
            float4 p;
            p.x = sc[i][0] * inv; p.y = sc[i][1] * inv;
            p.z = sc[i][2] * inv; p.w = sc[i][3] * inv;
            arow[i * 32 + lane] = p;
            float4 v0 = Vs[0 * SQ4 + i * 32 + lane];
            float4 v1 = Vs[1 * SQ4 + i * 32 + lane];
            float4 v2 = Vs[2 * SQ4 + i * 32 + lane];
            float4 v3 = Vs[3 * SQ4 + i * 32 + lane];
            ax += p.x * v0.x + p.y * v1.x + p.z * v2.x + p.w * v3.x;
            ay += p.x * v0.y + p.y * v1.y + p.z * v2.y + p.w * v3.y;
            az += p.x * v0.z + p.y * v1.z + p.z * v2.z + p.w * v3.z;
            aw += p.x * v0.w + p.y * v1.w + p.z * v2.w + p.w * v3.w;
        }
#pragma unroll
        for (int o = 16; o; o >>= 1) {
            ax += __shfl_xor_sync(0xffffffffu, ax, o);
            ay += __shfl_xor_sync(0xffffffffu, ay, o);
            az += __shfl_xor_sync(0xffffffffu, az, o);
            aw += __shfl_xor_sync(0xffffffffu, aw, o);
        }
        if (lane == 0) {
            float4 o4; o4.x = ax; o4.y = ay; o4.z = az; o4.w = aw;
            out[(size_t)bh * SQ + q] = o4;
        }
    }
}

extern "C" void kernel_launch(void* const* d_in, const int* in_sizes, int n_in,
                              void* d_out, int out_size)
{
    (void)in_sizes; (void)n_in; (void)out_size;
    const float4* Q    = (const float4*)d_in[0];
    const float4* K    = (const float4*)d_in[1];
    const float4* V    = (const float4*)d_in[2];
    const int*    mask = (const int*)   d_in[3];

    float* outp  = (float*)d_out;
    float* attnp = outp + (size_t)NB * NH * SQ * 4;   // attn follows out

    size_t smem = 2 * (size_t)SQ * sizeof(float4);    // 64 KB
    cudaFuncSetAttribute(mha_kernel, cudaFuncAttributeMaxDynamicSharedMemorySize, (int)smem);

    dim3 grid(SQ / QT, NB);
    mha_kernel<<<grid, THREADS, smem>>>(Q, K, V, mask,
                                        (float4*)outp, (float4*)attnp);
}